// round 14
// baseline (speedup 1.0000x reference)
#include <cuda_runtime.h>
#include <cstdint>
#include <math.h>

#define BATCH 2048
#define LAT   16
#define NC    23
#define HID0  16
#define HID1  32
#define NOUT  4000
#define CH    (NC*HID0)   // 368
#define CZ    (NC*HID1)   // 736
#define OUTW  (NC*NOUT)   // 92000
#define EPSN  1e-5f

#define NB1 64
#define NB3 128
#define ROWS3 16

#define TPT 9       // n-tiles (64 cols) per CTA in k5
#define NSTRIP 7    // 7*9*64 = 4032 >= 4000
#define BPITCH_B 144            // bytes per B smem row (128 data + 16 pad)
#define BBUF_B   (64*BPITCH_B)  // 9216 bytes per buffer
#define NRING 4

// ---------------- scratch (device globals; no allocation) ----------------
__device__ float g_p1[NB1][272];                  // per-block: sum_x[16], sum_xx[256]
__device__ __align__(16) float g_z[BATCH*CZ];     // pre-BN z   [2048, 736]
__device__ float g_p3[NB3][2*CZ];
__device__ __align__(16) float g_a0[CZ], g_c0[CZ];

__device__ __forceinline__ uint32_t smem_u32(const void* p) {
    uint32_t a;
    asm("{ .reg .u64 t; cvta.to.shared.u64 t, %1; cvt.u32.u64 %0, t; }" : "=r"(a) : "l"(p));
    return a;
}
__device__ __forceinline__ void gdc_wait() {
    asm volatile("griddepcontrol.wait;" ::: "memory");
}
__device__ __forceinline__ void gdc_launch() {
    asm volatile("griddepcontrol.launch_dependents;" ::: "memory");
}

// ---------------- K1: partial stats of x ----------------------------------
__global__ void k1_xstats(const float* __restrict__ x) {
    __shared__ float sx[32][LAT];
    int t = threadIdx.x;
    int r0 = blockIdx.x * 32;
    for (int i = t; i < 32*LAT; i += 256)
        sx[i >> 4][i & 15] = x[(r0 + (i >> 4))*LAT + (i & 15)];
    __syncthreads();
    int i = t >> 4, j = t & 15;
    float s = 0.f;
    #pragma unroll
    for (int r = 0; r < 32; r++) s += sx[r][i] * sx[r][j];
    g_p1[blockIdx.x][16 + t] = s;
    if (t < 16) {
        float sm = 0.f;
        #pragma unroll
        for (int r = 0; r < 32; r++) sm += sx[r][t];
        g_p1[blockIdx.x][t] = sm;
    }
}

// ---------------- K3: fused BN1-coef + BN1+leaky + grouped 16->32 ----------
// PDL restructure: the raw h = x@W1^T + b1 pass has NO dependency on k1 and
// runs BEFORE griddepcontrol.wait (overlapping k1). Post-wait: g_p1 reduce,
// BN1 coefs, in-place leaky(a1*h + c1) (same thread<->idx partition).
__global__ __launch_bounds__(256) void k3_z(
    const float* __restrict__ x, const float* __restrict__ W1,
    const float* __restrict__ b1, const float* __restrict__ g1,
    const float* __restrict__ be1, const float* __restrict__ W0,
    const float* __restrict__ b0) {
    __shared__ __align__(16) float shn[ROWS3][CH];
    __shared__ float raw[272];
    __shared__ float smu[16];
    __shared__ float scov[256];
    __shared__ float sa1[CH], sc1[CH];
    int t = threadIdx.x;
    int r0 = blockIdx.x * ROWS3;

    // ---- pre-wait: raw h for this block's 16 rows (pure x/W1 work)
    for (int idx = t; idx < ROWS3*CH; idx += 256) {
        int row = idx / CH, j = idx - row*CH;
        const float4* wp = (const float4*)(W1 + j*16);
        const float4* xp = (const float4*)(x + (size_t)(r0 + row)*16);
        float4 w0 = __ldg(wp+0), w1 = __ldg(wp+1), w2 = __ldg(wp+2), w3 = __ldg(wp+3);
        float4 x0 = __ldg(xp+0), x1 = __ldg(xp+1), x2 = __ldg(xp+2), x3 = __ldg(xp+3);
        float h = __ldg(&b1[j]);
        h = fmaf(w0.x,x0.x, fmaf(w0.y,x0.y, fmaf(w0.z,x0.z, fmaf(w0.w,x0.w, h))));
        h = fmaf(w1.x,x1.x, fmaf(w1.y,x1.y, fmaf(w1.z,x1.z, fmaf(w1.w,x1.w, h))));
        h = fmaf(w2.x,x2.x, fmaf(w2.y,x2.y, fmaf(w2.z,x2.z, fmaf(w2.w,x2.w, h))));
        h = fmaf(w3.x,x3.x, fmaf(w3.y,x3.y, fmaf(w3.z,x3.z, fmaf(w3.w,x3.w, h))));
        shn[row][j] = h;
    }

    gdc_wait();   // g_p1 from k1

    for (int i = t; i < 272; i += 256) {
        float s = 0.f;
        #pragma unroll 8
        for (int b = 0; b < NB1; b++) s += g_p1[b][i];
        raw[i] = s;
    }
    __syncthreads();
    if (t < 16) smu[t] = raw[t] * (1.f/BATCH);
    __syncthreads();
    if (t < 256) scov[t] = raw[16 + t] * (1.f/BATCH) - smu[t >> 4]*smu[t & 15];
    __syncthreads();
    for (int j = t; j < CH; j += 256) {
        float w[16];
        #pragma unroll
        for (int i = 0; i < 16; i++) w[i] = __ldg(&W1[j*16 + i]);
        float m = __ldg(&b1[j]);
        #pragma unroll
        for (int i = 0; i < 16; i++) m = fmaf(w[i], smu[i], m);
        float v = 0.f;
        #pragma unroll
        for (int i = 0; i < 16; i++) {
            float wi = w[i];
            #pragma unroll
            for (int k = 0; k < 16; k++) v = fmaf(wi * w[k], scov[i*16 + k], v);
        }
        float a = __ldg(&g1[j]) * rsqrtf(v + EPSN);
        sa1[j] = a;
        sc1[j] = __ldg(&be1[j]) - m * a;
    }
    __syncthreads();

    // ---- in-place: hn = leaky(a1*h + c1); same idx partition as pre-wait
    for (int idx = t; idx < ROWS3*CH; idx += 256) {
        int row = idx / CH, j = idx - row*CH;
        float v = fmaf(shn[row][j], sa1[j], sc1[j]);
        shn[row][j] = v >= 0.f ? v : 0.2f*v;
    }
    __syncthreads();

    for (int cc = t; cc < CZ; cc += 256) {
        int c = cc >> 5, o = cc & 31;
        const float4* wp = (const float4*)(W0 + (size_t)(c*32 + o)*16);
        float4 w0 = __ldg(wp+0), w1 = __ldg(wp+1), w2 = __ldg(wp+2), w3 = __ldg(wp+3);
        float bb = __ldg(&b0[cc]);
        float s1 = 0.f, s2 = 0.f;
        #pragma unroll 4
        for (int row = 0; row < ROWS3; row++) {
            const float4* hp = (const float4*)&shn[row][c*16];
            float4 h0 = hp[0], h1 = hp[1], h2 = hp[2], h3 = hp[3];
            float z = bb;
            z = fmaf(w0.x,h0.x, fmaf(w0.y,h0.y, fmaf(w0.z,h0.z, fmaf(w0.w,h0.w, z))));
            z = fmaf(w1.x,h1.x, fmaf(w1.y,h1.y, fmaf(w1.z,h1.z, fmaf(w1.w,h1.w, z))));
            z = fmaf(w2.x,h2.x, fmaf(w2.y,h2.y, fmaf(w2.z,h2.z, fmaf(w2.w,h2.w, z))));
            z = fmaf(w3.x,h3.x, fmaf(w3.y,h3.y, fmaf(w3.z,h3.z, fmaf(w3.w,h3.w, z))));
            g_z[(size_t)(r0 + row)*CZ + cc] = z;
            s1 += z; s2 = fmaf(z, z, s2);
        }
        g_p3[blockIdx.x][cc]      = s1;
        g_p3[blockIdx.x][CZ + cc] = s2;
    }
    gdc_launch();
}

// ---------------- K4: reduce z stats -> fused BN0 scale/shift --------------
__global__ void k4_bn0(const float* __restrict__ g0, const float* __restrict__ bb0) {
    __shared__ float r1[8][32], r2[8][32];
    int c = blockIdx.x;                          // 23 blocks x 256 threads
    int ch = threadIdx.x & 31, sl = threadIdx.x >> 5;
    gdc_wait();   // g_p3 from k3
    float s1 = 0.f, s2 = 0.f;
    #pragma unroll
    for (int k = 0; k < 16; k++) {
        int b = sl*16 + k;
        s1 += g_p3[b][c*32 + ch];
        s2 += g_p3[b][CZ + c*32 + ch];
    }
    r1[sl][ch] = s1; r2[sl][ch] = s2;
    __syncthreads();
    if (sl == 0) {
        #pragma unroll
        for (int k = 1; k < 8; k++) { s1 += r1[k][ch]; s2 += r2[k][ch]; }
        float mu  = s1 * (1.f/BATCH);
        float var = s2 * (1.f/BATCH) - mu*mu;
        float a = __ldg(&g0[c*32 + ch]) * rsqrtf(var + EPSN);
        g_a0[c*32 + ch] = a;
        g_c0[c*32 + ch] = __ldg(&bb0[c*32 + ch]) - mu * a;
    }
    gdc_launch();
}

// ---------------- K5: cp.async pipelined tf32 GEMM + tanh-sigmoid ----------
__device__ __forceinline__ float sigf(float v) {
    float th;
    asm("tanh.approx.f32 %0, %1;" : "=f"(th) : "f"(0.5f * v));
    return fmaf(0.5f, th, 0.5f);
}
__device__ __forceinline__ uint32_t tf32c(float v) {
    uint32_t u;
    asm("cvt.rna.tf32.f32 %0, %1;" : "=r"(u) : "f"(v));
    return u;
}

// CTA: m-tile 128, strip of TPT n-tiles of 64, 8 warps (4M x 2N), warp 32x32.
// B columns stored at PERMUTED physical smem rows (conflict-free reads).
// Ring deepened to 4 buffers / wait_group 2: one extra prefetch in flight.
__global__ __launch_bounds__(256, 3) void k5_mma(
    const float* __restrict__ W2, const float* __restrict__ b2,
    float* __restrict__ out) {
    __shared__ uint32_t AF[8*4*4*32];                    // 16 KB
    __shared__ __align__(16) char BR[NRING*BBUF_B];      // 36864 B raw B ring
    const int t = threadIdx.x;
    const int c  = blockIdx.z;
    const int m0 = blockIdx.y << 7;
    const int strip = blockIdx.x;
    const int nbase = strip*TPT*64;

    // ---- cp.async setup: 256 thr x 2 chunks of 16B cover 64 cols x 128B
    const int pr_col = t >> 3, pr_q = t & 7;   // source col 0..31 (+32 per s)
    const int pr_phys = 2*((pr_col >> 2) & 3) + (pr_col & 1)
                      + 8*((pr_col >> 1) & 1) + 16*((pr_col >> 4) & 1);
    const float* w2c  = W2 + (size_t)c*NOUT*32;
    const float* srcT = w2c + (size_t)(nbase + pr_col)*32 + pr_q*4;
    const uint32_t dstT = smem_u32(BR) + (uint32_t)(pr_phys*BPITCH_B + pr_q*16);

    #define ISSUE_B(TT, BUF) do {                                              \
        const float* s_ = srcT + (size_t)(TT)*64*32;                           \
        uint32_t d_ = dstT + (uint32_t)(BUF)*BBUF_B;                           \
        _Pragma("unroll")                                                      \
        for (int s = 0; s < 2; s++) {                                          \
            int o_ = nbase + (TT)*64 + pr_col + s*32;                          \
            const float* sp = s_ + s*32*32;                                    \
            unsigned sz = 16u;                                                 \
            if (o_ >= NOUT) { sp = w2c; sz = 0u; }                             \
            asm volatile("cp.async.cg.shared.global [%0], [%1], 16, %2;"       \
                         :: "r"(d_ + (uint32_t)(s*32*BPITCH_B)), "l"(sp),      \
                            "r"(sz) : "memory");                               \
        }                                                                      \
        asm volatile("cp.async.commit_group;" ::: "memory");                   \
    } while (0)

    ISSUE_B(0, 0);
    ISSUE_B(1, 1);
    ISSUE_B(2, 2);

    gdc_wait();   // g_z (k3) + g_a0/g_c0 (k4) must be visible beyond here

    // ---- A producer: leaky(a0*z + c0) -> tf32 frags (once per CTA)
    #pragma unroll
    for (int s = 0; s < 4; s++) {
        int i = t + s*256;            // 1024 float4s: 128 rows x 8 quads
        int row = i >> 3, q = i & 7;
        float4 z4 = *(const float4*)&g_z[(size_t)(m0 + row)*CZ + c*32 + q*4];
        float4 a4 = *(const float4*)&g_a0[c*32 + q*4];
        float4 c4 = *(const float4*)&g_c0[c*32 + q*4];
        float v0 = fmaf(z4.x, a4.x, c4.x); v0 = v0 >= 0.f ? v0 : 0.2f*v0;
        float v1 = fmaf(z4.y, a4.y, c4.y); v1 = v1 >= 0.f ? v1 : 0.2f*v1;
        float v2 = fmaf(z4.z, a4.z, c4.z); v2 = v2 >= 0.f ? v2 : 0.2f*v2;
        float v3 = fmaf(z4.w, a4.w, c4.w); v3 = v3 >= 0.f ? v3 : 0.2f*v3;
        int msub = row >> 4, r = row & 15;
        int kstep = q >> 1;
        int reg = (r >= 8 ? 1 : 0) + ((q & 1) << 1);
        uint4 u = make_uint4(tf32c(v0), tf32c(v1), tf32c(v2), tf32c(v3));
        *(uint4*)&AF[(((msub*4 + kstep)*4 + reg)*32) + ((r & 7) << 2)] = u;
    }
    __syncthreads();

    const int wid = t >> 5, l = t & 31;
    const int wm = wid & 3, wn = wid >> 2;
    const int g = l >> 2, q4 = l & 3;

    // ---- A fragments into registers for the whole strip
    uint32_t areg[2][4][4];
    #pragma unroll
    for (int ms = 0; ms < 2; ms++)
        #pragma unroll
        for (int kstep = 0; kstep < 4; kstep++)
            #pragma unroll
            for (int r = 0; r < 4; r++)
                areg[ms][kstep][r] = AF[(((wm*2 + ms)*4 + kstep)*4 + r)*32 + l];

    // ---- mainloop read base: physical row = wn*32 + p3 (+ imm ns offsets)
    const int p3 = l >> 2;
    const char* rbase0 = BR + (wn*32 + p3)*BPITCH_B + (l & 3)*4;

    // ---- incremental output/bias pointers
    float* op0 = out + (size_t)(m0 + wm*32 + g)*OUTW + (size_t)c*NOUT
                     + nbase + wn*32 + 4*q4;
    float* opB = op0 + (size_t)16*OUTW;
    const float* bp = b2 + (size_t)c*NOUT + nbase + wn*32 + 4*q4;
    int ncol = nbase + wn*32 + 4*q4;

    for (int tt = 0; tt < TPT; tt++) {
        if (tt < TPT-2)      asm volatile("cp.async.wait_group 2;" ::: "memory");
        else if (tt == TPT-2) asm volatile("cp.async.wait_group 1;" ::: "memory");
        else                 asm volatile("cp.async.wait_group 0;" ::: "memory");
        __syncthreads();
        if (tt + 3 < TPT) {
            ISSUE_B(tt + 3, (tt + 3) & 3);
        }

        const char* rb = rbase0 + (tt & 3)*BBUF_B;

        // ---- mainloop: raw LDS (conflict-free) + cvt.rna + HMMA
        float acc[2][4][4];
        #pragma unroll
        for (int ms = 0; ms < 2; ms++)
            #pragma unroll
            for (int ns = 0; ns < 4; ns++)
                #pragma unroll
                for (int r = 0; r < 4; r++) acc[ms][ns][r] = 0.f;

        #pragma unroll
        for (int kstep = 0; kstep < 4; kstep++) {
            uint32_t b[4][2];
            #pragma unroll
            for (int ns = 0; ns < 4; ns++) {
                #pragma unroll
                for (int r = 0; r < 2; r++) {
                    float rawv = *(const float*)(rb + (ns >> 1)*(16*BPITCH_B)
                                                 + (ns & 1)*(8*BPITCH_B)
                                                 + kstep*32 + r*16);
                    b[ns][r] = tf32c(rawv);
                }
            }
            #pragma unroll
            for (int ms = 0; ms < 2; ms++)
                #pragma unroll
                for (int ns = 0; ns < 4; ns++)
                    asm volatile(
                        "mma.sync.aligned.m16n8k8.row.col.f32.tf32.tf32.f32 "
                        "{%0,%1,%2,%3}, {%4,%5,%6,%7}, {%8,%9}, {%0,%1,%2,%3};"
                        : "+f"(acc[ms][ns][0]), "+f"(acc[ms][ns][1]),
                          "+f"(acc[ms][ns][2]), "+f"(acc[ms][ns][3])
                        : "r"(areg[ms][kstep][0]), "r"(areg[ms][kstep][1]),
                          "r"(areg[ms][kstep][2]), "r"(areg[ms][kstep][3]),
                          "r"(b[ns][0]), "r"(b[ns][1]));
        }

        // ---- epilogue: bias + tanh-sigmoid + plain float4 stores (R8 form)
        #pragma unroll
        for (int j = 0; j < 2; j++) {
            if (ncol + 16*j < NOUT) {
                float4 bb = *(const float4*)(bp + 16*j);
                float4 o;
                o.x = sigf(acc[0][2*j  ][0] + bb.x);
                o.y = sigf(acc[0][2*j  ][1] + bb.y);
                o.z = sigf(acc[0][2*j+1][0] + bb.z);
                o.w = sigf(acc[0][2*j+1][1] + bb.w);
                *(float4*)(op0 + 16*j) = o;
                o.x = sigf(acc[0][2*j  ][2] + bb.x);
                o.y = sigf(acc[0][2*j  ][3] + bb.y);
                o.z = sigf(acc[0][2*j+1][2] + bb.z);
                o.w = sigf(acc[0][2*j+1][3] + bb.w);
                *(float4*)(op0 + (size_t)8*OUTW + 16*j) = o;
                o.x = sigf(acc[1][2*j  ][0] + bb.x);
                o.y = sigf(acc[1][2*j  ][1] + bb.y);
                o.z = sigf(acc[1][2*j+1][0] + bb.z);
                o.w = sigf(acc[1][2*j+1][1] + bb.w);
                *(float4*)(opB + 16*j) = o;
                o.x = sigf(acc[1][2*j  ][2] + bb.x);
                o.y = sigf(acc[1][2*j  ][3] + bb.y);
                o.z = sigf(acc[1][2*j+1][2] + bb.z);
                o.w = sigf(acc[1][2*j+1][3] + bb.w);
                *(float4*)(opB + (size_t)8*OUTW + 16*j) = o;
            }
        }
        op0 += 64; opB += 64; bp += 64; ncol += 64;
    }
    #undef ISSUE_B
}

// ---------------- launch ---------------------------------------------------
static void launch_pdl(const void* fn, dim3 gd, dim3 bd, void** args) {
    cudaLaunchConfig_t cfg = {};
    cfg.gridDim = gd;
    cfg.blockDim = bd;
    cfg.dynamicSmemBytes = 0;
    cfg.stream = 0;
    cudaLaunchAttribute at[1];
    at[0].id = cudaLaunchAttributeProgrammaticStreamSerialization;
    at[0].val.programmaticStreamSerializationAllowed = 1;
    cfg.attrs = at;
    cfg.numAttrs = 1;
    cudaLaunchKernelExC(&cfg, fn, args);
}

extern "C" void kernel_launch(void* const* d_in, const int* in_sizes, int n_in,
                              void* d_out, int out_size) {
    const float* x   = (const float*)d_in[0];
    const float* W1  = (const float*)d_in[1];
    const float* b1  = (const float*)d_in[2];
    const float* g1  = (const float*)d_in[3];
    const float* be1 = (const float*)d_in[4];
    const float* W0  = (const float*)d_in[5];
    const float* b0  = (const float*)d_in[6];
    const float* g0  = (const float*)d_in[7];
    const float* bb0 = (const float*)d_in[8];
    const float* W2  = (const float*)d_in[9];
    const float* b2  = (const float*)d_in[10];
    float* out = (float*)d_out;

    k1_xstats<<<NB1, 256>>>(x);

    void* a3[] = {(void*)&x, (void*)&W1, (void*)&b1, (void*)&g1,
                  (void*)&be1, (void*)&W0, (void*)&b0};
    launch_pdl((const void*)k3_z, dim3(NB3,1,1), dim3(256,1,1), a3);

    void* a4[] = {(void*)&g0, (void*)&bb0};
    launch_pdl((const void*)k4_bn0, dim3(NC,1,1), dim3(256,1,1), a4);

    void* a5[] = {(void*)&W2, (void*)&b2, (void*)&out};
    launch_pdl((const void*)k5_mma, dim3(NSTRIP, BATCH/128, NC), dim3(256,1,1), a5);
}

// round 15
// speedup vs baseline: 1.0118x; 1.0118x over previous
#include <cuda_runtime.h>
#include <cstdint>
#include <math.h>

#define BATCH 2048
#define LAT   16
#define NC    23
#define HID0  16
#define HID1  32
#define NOUT  4000
#define CH    (NC*HID0)   // 368
#define CZ    (NC*HID1)   // 736
#define OUTW  (NC*NOUT)   // 92000
#define EPSN  1e-5f

#define NB1 64
#define NB3 128
#define ROWS3 16

#define TPT 9       // n-tiles (64 cols) per CTA in k5
#define NSTRIP 7    // 7*9*64 = 4032 >= 4000
#define BPITCH_B 144            // bytes per B smem row (128 data + 16 pad)
#define BBUF_B   (64*BPITCH_B)  // 9216 bytes per buffer

// ---------------- scratch (device globals; no allocation) ----------------
__device__ float g_p1[NB1][272];                  // per-block: sum_x[16], sum_xx[256]
__device__ __align__(16) float g_z[BATCH*CZ];     // pre-BN z   [2048, 736]
__device__ float g_p3[NB3][2*CZ];
__device__ __align__(16) float g_a0[CZ], g_c0[CZ];

__device__ __forceinline__ uint32_t smem_u32(const void* p) {
    uint32_t a;
    asm("{ .reg .u64 t; cvta.to.shared.u64 t, %1; cvt.u32.u64 %0, t; }" : "=r"(a) : "l"(p));
    return a;
}
__device__ __forceinline__ void gdc_wait() {
    asm volatile("griddepcontrol.wait;" ::: "memory");
}
__device__ __forceinline__ void gdc_launch() {
    asm volatile("griddepcontrol.launch_dependents;" ::: "memory");
}

// ---------------- K1: partial stats of x ----------------------------------
__global__ void k1_xstats(const float* __restrict__ x) {
    __shared__ float sx[32][LAT];
    gdc_launch();            // let k3 launch immediately (its pre-wait work
                             // has no dependency on k1; gdc_wait protects it)
    int t = threadIdx.x;
    int r0 = blockIdx.x * 32;
    for (int i = t; i < 32*LAT; i += 256)
        sx[i >> 4][i & 15] = x[(r0 + (i >> 4))*LAT + (i & 15)];
    __syncthreads();
    int i = t >> 4, j = t & 15;
    float s = 0.f;
    #pragma unroll
    for (int r = 0; r < 32; r++) s += sx[r][i] * sx[r][j];
    g_p1[blockIdx.x][16 + t] = s;
    if (t < 16) {
        float sm = 0.f;
        #pragma unroll
        for (int r = 0; r < 32; r++) sm += sx[r][t];
        g_p1[blockIdx.x][t] = sm;
    }
}

// ---------------- K3: fused BN1-coef + BN1+leaky + grouped 16->32 ----------
// Pre-wait: raw h = x@W1^T + b1 (no k1 dependency) overlaps k1.
// Post-wait: g_p1 reduce, BN1 coefs, in-place leaky, grouped GEMM.
__global__ __launch_bounds__(256) void k3_z(
    const float* __restrict__ x, const float* __restrict__ W1,
    const float* __restrict__ b1, const float* __restrict__ g1,
    const float* __restrict__ be1, const float* __restrict__ W0,
    const float* __restrict__ b0) {
    __shared__ __align__(16) float shn[ROWS3][CH];
    __shared__ float raw[272];
    __shared__ float smu[16];
    __shared__ float scov[256];
    __shared__ float sa1[CH], sc1[CH];
    int t = threadIdx.x;
    int r0 = blockIdx.x * ROWS3;

    // ---- pre-wait: raw h for this block's 16 rows (pure x/W1 work)
    for (int idx = t; idx < ROWS3*CH; idx += 256) {
        int row = idx / CH, j = idx - row*CH;
        const float4* wp = (const float4*)(W1 + j*16);
        const float4* xp = (const float4*)(x + (size_t)(r0 + row)*16);
        float4 w0 = __ldg(wp+0), w1 = __ldg(wp+1), w2 = __ldg(wp+2), w3 = __ldg(wp+3);
        float4 x0 = __ldg(xp+0), x1 = __ldg(xp+1), x2 = __ldg(xp+2), x3 = __ldg(xp+3);
        float h = __ldg(&b1[j]);
        h = fmaf(w0.x,x0.x, fmaf(w0.y,x0.y, fmaf(w0.z,x0.z, fmaf(w0.w,x0.w, h))));
        h = fmaf(w1.x,x1.x, fmaf(w1.y,x1.y, fmaf(w1.z,x1.z, fmaf(w1.w,x1.w, h))));
        h = fmaf(w2.x,x2.x, fmaf(w2.y,x2.y, fmaf(w2.z,x2.z, fmaf(w2.w,x2.w, h))));
        h = fmaf(w3.x,x3.x, fmaf(w3.y,x3.y, fmaf(w3.z,x3.z, fmaf(w3.w,x3.w, h))));
        shn[row][j] = h;
    }

    gdc_wait();     // k1 fully complete: g_p1 visible
    gdc_launch();   // let k4 (and transitively k5) launch early

    for (int i = t; i < 272; i += 256) {
        float s = 0.f;
        #pragma unroll 8
        for (int b = 0; b < NB1; b++) s += g_p1[b][i];
        raw[i] = s;
    }
    __syncthreads();
    if (t < 16) smu[t] = raw[t] * (1.f/BATCH);
    __syncthreads();
    if (t < 256) scov[t] = raw[16 + t] * (1.f/BATCH) - smu[t >> 4]*smu[t & 15];
    __syncthreads();
    for (int j = t; j < CH; j += 256) {
        float w[16];
        #pragma unroll
        for (int i = 0; i < 16; i++) w[i] = __ldg(&W1[j*16 + i]);
        float m = __ldg(&b1[j]);
        #pragma unroll
        for (int i = 0; i < 16; i++) m = fmaf(w[i], smu[i], m);
        float v = 0.f;
        #pragma unroll
        for (int i = 0; i < 16; i++) {
            float wi = w[i];
            #pragma unroll
            for (int k = 0; k < 16; k++) v = fmaf(wi * w[k], scov[i*16 + k], v);
        }
        float a = __ldg(&g1[j]) * rsqrtf(v + EPSN);
        sa1[j] = a;
        sc1[j] = __ldg(&be1[j]) - m * a;
    }
    __syncthreads();

    // ---- in-place: hn = leaky(a1*h + c1); same idx partition as pre-wait
    for (int idx = t; idx < ROWS3*CH; idx += 256) {
        int row = idx / CH, j = idx - row*CH;
        float v = fmaf(shn[row][j], sa1[j], sc1[j]);
        shn[row][j] = v >= 0.f ? v : 0.2f*v;
    }
    __syncthreads();

    for (int cc = t; cc < CZ; cc += 256) {
        int c = cc >> 5, o = cc & 31;
        const float4* wp = (const float4*)(W0 + (size_t)(c*32 + o)*16);
        float4 w0 = __ldg(wp+0), w1 = __ldg(wp+1), w2 = __ldg(wp+2), w3 = __ldg(wp+3);
        float bb = __ldg(&b0[cc]);
        float s1 = 0.f, s2 = 0.f;
        #pragma unroll 4
        for (int row = 0; row < ROWS3; row++) {
            const float4* hp = (const float4*)&shn[row][c*16];
            float4 h0 = hp[0], h1 = hp[1], h2 = hp[2], h3 = hp[3];
            float z = bb;
            z = fmaf(w0.x,h0.x, fmaf(w0.y,h0.y, fmaf(w0.z,h0.z, fmaf(w0.w,h0.w, z))));
            z = fmaf(w1.x,h1.x, fmaf(w1.y,h1.y, fmaf(w1.z,h1.z, fmaf(w1.w,h1.w, z))));
            z = fmaf(w2.x,h2.x, fmaf(w2.y,h2.y, fmaf(w2.z,h2.z, fmaf(w2.w,h2.w, z))));
            z = fmaf(w3.x,h3.x, fmaf(w3.y,h3.y, fmaf(w3.z,h3.z, fmaf(w3.w,h3.w, z))));
            g_z[(size_t)(r0 + row)*CZ + cc] = z;
            s1 += z; s2 = fmaf(z, z, s2);
        }
        g_p3[blockIdx.x][cc]      = s1;
        g_p3[blockIdx.x][CZ + cc] = s2;
    }
}

// ---------------- K4: reduce z stats -> fused BN0 scale/shift --------------
__global__ void k4_bn0(const float* __restrict__ g0, const float* __restrict__ bb0) {
    __shared__ float r1[8][32], r2[8][32];
    int c = blockIdx.x;                          // 23 blocks x 256 threads
    int ch = threadIdx.x & 31, sl = threadIdx.x >> 5;
    gdc_wait();     // g_p3 from k3
    gdc_launch();   // let k5 launch: its W2 prefetches need nothing upstream
    float s1 = 0.f, s2 = 0.f;
    #pragma unroll
    for (int k = 0; k < 16; k++) {
        int b = sl*16 + k;
        s1 += g_p3[b][c*32 + ch];
        s2 += g_p3[b][CZ + c*32 + ch];
    }
    r1[sl][ch] = s1; r2[sl][ch] = s2;
    __syncthreads();
    if (sl == 0) {
        #pragma unroll
        for (int k = 1; k < 8; k++) { s1 += r1[k][ch]; s2 += r2[k][ch]; }
        float mu  = s1 * (1.f/BATCH);
        float var = s2 * (1.f/BATCH) - mu*mu;
        float a = __ldg(&g0[c*32 + ch]) * rsqrtf(var + EPSN);
        g_a0[c*32 + ch] = a;
        g_c0[c*32 + ch] = __ldg(&bb0[c*32 + ch]) - mu * a;
    }
}

// ---------------- K5: cp.async pipelined tf32 GEMM + tanh-sigmoid ----------
__device__ __forceinline__ float sigf(float v) {
    float th;
    asm("tanh.approx.f32 %0, %1;" : "=f"(th) : "f"(0.5f * v));
    return fmaf(0.5f, th, 0.5f);
}
__device__ __forceinline__ uint32_t tf32c(float v) {
    uint32_t u;
    asm("cvt.rna.tf32.f32 %0, %1;" : "=r"(u) : "f"(v));
    return u;
}

// CTA: m-tile 128, strip of TPT n-tiles of 64, 8 warps (4M x 2N), warp 32x32.
// B columns stored at PERMUTED physical smem rows (conflict-free reads).
// Ring of 3 (measured best in R13). W2 prefetches issue pre-wait.
__global__ __launch_bounds__(256, 3) void k5_mma(
    const float* __restrict__ W2, const float* __restrict__ b2,
    float* __restrict__ out) {
    __shared__ uint32_t AF[8*4*4*32];                    // 16 KB
    __shared__ __align__(16) char BR[3*BBUF_B];          // 27648 B raw B ring
    const int t = threadIdx.x;
    const int c  = blockIdx.z;
    const int m0 = blockIdx.y << 7;
    const int strip = blockIdx.x;
    const int nbase = strip*TPT*64;

    // ---- cp.async setup: 256 thr x 2 chunks of 16B cover 64 cols x 128B
    const int pr_col = t >> 3, pr_q = t & 7;   // source col 0..31 (+32 per s)
    const int pr_phys = 2*((pr_col >> 2) & 3) + (pr_col & 1)
                      + 8*((pr_col >> 1) & 1) + 16*((pr_col >> 4) & 1);
    const float* w2c  = W2 + (size_t)c*NOUT*32;
    const float* srcT = w2c + (size_t)(nbase + pr_col)*32 + pr_q*4;
    const uint32_t dstT = smem_u32(BR) + (uint32_t)(pr_phys*BPITCH_B + pr_q*16);

    #define ISSUE_B(TT, BUF) do {                                              \
        const float* s_ = srcT + (size_t)(TT)*64*32;                           \
        uint32_t d_ = dstT + (uint32_t)(BUF)*BBUF_B;                           \
        _Pragma("unroll")                                                      \
        for (int s = 0; s < 2; s++) {                                          \
            int o_ = nbase + (TT)*64 + pr_col + s*32;                          \
            const float* sp = s_ + s*32*32;                                    \
            unsigned sz = 16u;                                                 \
            if (o_ >= NOUT) { sp = w2c; sz = 0u; }                             \
            asm volatile("cp.async.cg.shared.global [%0], [%1], 16, %2;"       \
                         :: "r"(d_ + (uint32_t)(s*32*BPITCH_B)), "l"(sp),      \
                            "r"(sz) : "memory");                               \
        }                                                                      \
        asm volatile("cp.async.commit_group;" ::: "memory");                   \
    } while (0)

    ISSUE_B(0, 0);
    ISSUE_B(1, 1);

    gdc_wait();   // g_z (k3) + g_a0/g_c0 (k4) must be visible beyond here

    // ---- A producer: leaky(a0*z + c0) -> tf32 frags (once per CTA)
    #pragma unroll
    for (int s = 0; s < 4; s++) {
        int i = t + s*256;            // 1024 float4s: 128 rows x 8 quads
        int row = i >> 3, q = i & 7;
        float4 z4 = *(const float4*)&g_z[(size_t)(m0 + row)*CZ + c*32 + q*4];
        float4 a4 = *(const float4*)&g_a0[c*32 + q*4];
        float4 c4 = *(const float4*)&g_c0[c*32 + q*4];
        float v0 = fmaf(z4.x, a4.x, c4.x); v0 = v0 >= 0.f ? v0 : 0.2f*v0;
        float v1 = fmaf(z4.y, a4.y, c4.y); v1 = v1 >= 0.f ? v1 : 0.2f*v1;
        float v2 = fmaf(z4.z, a4.z, c4.z); v2 = v2 >= 0.f ? v2 : 0.2f*v2;
        float v3 = fmaf(z4.w, a4.w, c4.w); v3 = v3 >= 0.f ? v3 : 0.2f*v3;
        int msub = row >> 4, r = row & 15;
        int kstep = q >> 1;
        int reg = (r >= 8 ? 1 : 0) + ((q & 1) << 1);
        uint4 u = make_uint4(tf32c(v0), tf32c(v1), tf32c(v2), tf32c(v3));
        *(uint4*)&AF[(((msub*4 + kstep)*4 + reg)*32) + ((r & 7) << 2)] = u;
    }
    __syncthreads();

    const int wid = t >> 5, l = t & 31;
    const int wm = wid & 3, wn = wid >> 2;
    const int g = l >> 2, q4 = l & 3;

    // ---- A fragments into registers for the whole strip
    uint32_t areg[2][4][4];
    #pragma unroll
    for (int ms = 0; ms < 2; ms++)
        #pragma unroll
        for (int kstep = 0; kstep < 4; kstep++)
            #pragma unroll
            for (int r = 0; r < 4; r++)
                areg[ms][kstep][r] = AF[(((wm*2 + ms)*4 + kstep)*4 + r)*32 + l];

    // ---- mainloop read base: physical row = wn*32 + p3 (+ imm ns offsets)
    const int p3 = l >> 2;
    const char* rbase0 = BR + (wn*32 + p3)*BPITCH_B + (l & 3)*4;

    // ---- incremental output/bias pointers
    float* op0 = out + (size_t)(m0 + wm*32 + g)*OUTW + (size_t)c*NOUT
                     + nbase + wn*32 + 4*q4;
    float* opB = op0 + (size_t)16*OUTW;
    const float* bp = b2 + (size_t)c*NOUT + nbase + wn*32 + 4*q4;
    int ncol = nbase + wn*32 + 4*q4;

    for (int tt = 0; tt < TPT; tt++) {
        if (tt < TPT-1) asm volatile("cp.async.wait_group 1;" ::: "memory");
        else            asm volatile("cp.async.wait_group 0;" ::: "memory");
        __syncthreads();
        if (tt + 2 < TPT) {
            int b3 = tt + 2; b3 -= (b3 >= 3) ? 3 : 0; b3 -= (b3 >= 3) ? 3 : 0;
            ISSUE_B(tt + 2, b3);
        }

        int cb = tt; cb -= (cb >= 3) ? 3 : 0; cb -= (cb >= 3) ? 3 : 0;
        cb -= (cb >= 3) ? 3 : 0;
        const char* rb = rbase0 + cb*BBUF_B;

        // ---- mainloop: raw LDS (conflict-free) + cvt.rna + HMMA
        float acc[2][4][4];
        #pragma unroll
        for (int ms = 0; ms < 2; ms++)
            #pragma unroll
            for (int ns = 0; ns < 4; ns++)
                #pragma unroll
                for (int r = 0; r < 4; r++) acc[ms][ns][r] = 0.f;

        #pragma unroll
        for (int kstep = 0; kstep < 4; kstep++) {
            uint32_t b[4][2];
            #pragma unroll
            for (int ns = 0; ns < 4; ns++) {
                #pragma unroll
                for (int r = 0; r < 2; r++) {
                    float rawv = *(const float*)(rb + (ns >> 1)*(16*BPITCH_B)
                                                 + (ns & 1)*(8*BPITCH_B)
                                                 + kstep*32 + r*16);
                    b[ns][r] = tf32c(rawv);
                }
            }
            #pragma unroll
            for (int ms = 0; ms < 2; ms++)
                #pragma unroll
                for (int ns = 0; ns < 4; ns++)
                    asm volatile(
                        "mma.sync.aligned.m16n8k8.row.col.f32.tf32.tf32.f32 "
                        "{%0,%1,%2,%3}, {%4,%5,%6,%7}, {%8,%9}, {%0,%1,%2,%3};"
                        : "+f"(acc[ms][ns][0]), "+f"(acc[ms][ns][1]),
                          "+f"(acc[ms][ns][2]), "+f"(acc[ms][ns][3])
                        : "r"(areg[ms][kstep][0]), "r"(areg[ms][kstep][1]),
                          "r"(areg[ms][kstep][2]), "r"(areg[ms][kstep][3]),
                          "r"(b[ns][0]), "r"(b[ns][1]));
        }

        // ---- epilogue: bias + tanh-sigmoid + plain float4 stores (R8 form)
        #pragma unroll
        for (int j = 0; j < 2; j++) {
            if (ncol + 16*j < NOUT) {
                float4 bb = *(const float4*)(bp + 16*j);
                float4 o;
                o.x = sigf(acc[0][2*j  ][0] + bb.x);
                o.y = sigf(acc[0][2*j  ][1] + bb.y);
                o.z = sigf(acc[0][2*j+1][0] + bb.z);
                o.w = sigf(acc[0][2*j+1][1] + bb.w);
                *(float4*)(op0 + 16*j) = o;
                o.x = sigf(acc[0][2*j  ][2] + bb.x);
                o.y = sigf(acc[0][2*j  ][3] + bb.y);
                o.z = sigf(acc[0][2*j+1][2] + bb.z);
                o.w = sigf(acc[0][2*j+1][3] + bb.w);
                *(float4*)(op0 + (size_t)8*OUTW + 16*j) = o;
                o.x = sigf(acc[1][2*j  ][0] + bb.x);
                o.y = sigf(acc[1][2*j  ][1] + bb.y);
                o.z = sigf(acc[1][2*j+1][0] + bb.z);
                o.w = sigf(acc[1][2*j+1][1] + bb.w);
                *(float4*)(opB + 16*j) = o;
                o.x = sigf(acc[1][2*j  ][2] + bb.x);
                o.y = sigf(acc[1][2*j  ][3] + bb.y);
                o.z = sigf(acc[1][2*j+1][2] + bb.z);
                o.w = sigf(acc[1][2*j+1][3] + bb.w);
                *(float4*)(opB + (size_t)8*OUTW + 16*j) = o;
            }
        }
        op0 += 64; opB += 64; bp += 64; ncol += 64;
    }
    #undef ISSUE_B
}

// ---------------- launch ---------------------------------------------------
static void launch_pdl(const void* fn, dim3 gd, dim3 bd, void** args) {
    cudaLaunchConfig_t cfg = {};
    cfg.gridDim = gd;
    cfg.blockDim = bd;
    cfg.dynamicSmemBytes = 0;
    cfg.stream = 0;
    cudaLaunchAttribute at[1];
    at[0].id = cudaLaunchAttributeProgrammaticStreamSerialization;
    at[0].val.programmaticStreamSerializationAllowed = 1;
    cfg.attrs = at;
    cfg.numAttrs = 1;
    cudaLaunchKernelExC(&cfg, fn, args);
}

extern "C" void kernel_launch(void* const* d_in, const int* in_sizes, int n_in,
                              void* d_out, int out_size) {
    const float* x   = (const float*)d_in[0];
    const float* W1  = (const float*)d_in[1];
    const float* b1  = (const float*)d_in[2];
    const float* g1  = (const float*)d_in[3];
    const float* be1 = (const float*)d_in[4];
    const float* W0  = (const float*)d_in[5];
    const float* b0  = (const float*)d_in[6];
    const float* g0  = (const float*)d_in[7];
    const float* bb0 = (const float*)d_in[8];
    const float* W2  = (const float*)d_in[9];
    const float* b2  = (const float*)d_in[10];
    float* out = (float*)d_out;

    k1_xstats<<<NB1, 256>>>(x);

    void* a3[] = {(void*)&x, (void*)&W1, (void*)&b1, (void*)&g1,
                  (void*)&be1, (void*)&W0, (void*)&b0};
    launch_pdl((const void*)k3_z, dim3(NB3,1,1), dim3(256,1,1), a3);

    void* a4[] = {(void*)&g0, (void*)&bb0};
    launch_pdl((const void*)k4_bn0, dim3(NC,1,1), dim3(256,1,1), a4);

    void* a5[] = {(void*)&W2, (void*)&b2, (void*)&out};
    launch_pdl((const void*)k5_mma, dim3(NSTRIP, BATCH/128, NC), dim3(256,1,1), a5);
}